// round 17
// baseline (speedup 1.0000x reference)
#include <cuda_runtime.h>
#include <cuda_bf16.h>
#include <math.h>

// Problem constants (fixed by the reference)
#define BN    8192
#define CN    2048
#define LN    6
#define HALF  4096
#define MN    (BN + LN)          // 8198
#define XOUT_ELEMS ((size_t)MN * CN)
#define ADJ_OFF    XOUT_ELEMS

#define G     4                  // rows staged per group (pass)
#define NGRP  16                 // groups per block (64 rows/block, grid 128)

// ---- scratch (no allocations allowed) ----
__device__ float g_U[LN * CN];   // sum_n s_n * x_n per cam
__device__ float g_denom[LN];    // per-cam sum of scores
__device__ float g_cnt[LN];      // per-cam counts

// ---------------------------------------------------------------------------
// 0) zero the scratch accumulators (graph replays reuse them)
// ---------------------------------------------------------------------------
__global__ void zero_kernel() {
    int idx = blockIdx.x * blockDim.x + threadIdx.x;
    if (idx < LN * CN) g_U[idx] = 0.0f;
    if (idx < LN) { g_denom[idx] = 0.0f; g_cnt[idx] = 0.0f; }
}

// ---------------------------------------------------------------------------
// 1) pass (R8 group-staged body MINUS the x->out copy — that moved to a
//    copy-engine memcpy): pure read + score + weighted accumulation.
// ---------------------------------------------------------------------------
__global__ void __launch_bounds__(256) pass_kernel(
    const float* __restrict__ x, const int* __restrict__ cams,
    const float* __restrict__ att_w, const float* __restrict__ att_b)
{
    __shared__ float sx[G][CN];      // 32 KB staged rows
    __shared__ float sscore[G];
    __shared__ int   scam[G];
    __shared__ float sden[LN];
    __shared__ float scnt[LN];

    const int t = threadIdx.x;
    const int w = t >> 5, lane = t & 31;
    if (t < LN) { sden[t] = 0.0f; scnt[t] = 0.0f; }

    float acc[LN][8];
#pragma unroll
    for (int l = 0; l < LN; ++l)
#pragma unroll
        for (int k = 0; k < 8; ++k) acc[l][k] = 0.0f;

    const int r0 = blockIdx.x * (G * NGRP);          // 64 rows per block
    const float4* __restrict__ x4 = (const float4*)x;
    const float4* __restrict__ w4 = (const float4*)att_w;

    float4 buf[8];
#pragma unroll
    for (int m = 0; m < 8; ++m) {
        const int f = t + 256 * m;
        buf[m] = x4[(size_t)(r0 + (f >> 9)) * 512 + (f & 511)];
    }

    for (int g = 0; g < NGRP; ++g) {
        const int rows = r0 + G * g;

        __syncthreads();

#pragma unroll
        for (int m = 0; m < 8; ++m) {
            const int f = t + 256 * m;
            const int rig = f >> 9, c4 = f & 511;
            *(float4*)&sx[rig][4 * c4] = buf[m];
        }
        if (t < G) scam[t] = __ldg(&cams[rows + t]);
        __syncthreads();

        if (w < G) {
            const int cam = scam[w];
            float s = 0.0f;
#pragma unroll
            for (int k = 0; k < 16; ++k) {
                const int c4 = lane + 32 * k;
                const float4 xv = *(const float4*)&sx[w][4 * c4];
                const float4 wv = __ldg(&w4[(size_t)cam * 512 + c4]);
                s += xv.x * wv.x + xv.y * wv.y + xv.z * wv.z + xv.w * wv.w;
            }
#pragma unroll
            for (int o = 16; o > 0; o >>= 1) s += __shfl_down_sync(0xffffffffu, s, o);
            if (lane == 0) {
                s += __ldg(&att_b[cam]);
                sscore[w] = s;
                atomicAdd(&sden[cam], s);
                atomicAdd(&scnt[cam], 1.0f);
            }
        }
        __syncthreads();

        if (g + 1 < NGRP) {
#pragma unroll
            for (int m = 0; m < 8; ++m) {
                const int f = t + 256 * m;
                buf[m] = x4[(size_t)(rows + G + (f >> 9)) * 512 + (f & 511)];
            }
        }

#pragma unroll
        for (int r = 0; r < G; ++r) {
            const float s = sscore[r];
            const int cam = scam[r];
            const float4 xa = *(const float4*)&sx[r][4 * t];
            const float4 xb = *(const float4*)&sx[r][1024 + 4 * t];
#pragma unroll
            for (int l = 0; l < LN; ++l) {
                const float sl = (cam == l) ? s : 0.0f;
                acc[l][0] += sl * xa.x;  acc[l][1] += sl * xa.y;
                acc[l][2] += sl * xa.z;  acc[l][3] += sl * xa.w;
                acc[l][4] += sl * xb.x;  acc[l][5] += sl * xb.y;
                acc[l][6] += sl * xb.z;  acc[l][7] += sl * xb.w;
            }
        }
    }

#pragma unroll
    for (int l = 0; l < LN; ++l) {
#pragma unroll
        for (int k = 0; k < 4; ++k)
            atomicAdd(&g_U[l * CN + 4 * t + k], acc[l][k]);
#pragma unroll
        for (int k = 0; k < 4; ++k)
            atomicAdd(&g_U[l * CN + 1024 + 4 * t + k], acc[l][k + 4]);
    }
    if (t < LN) {
        atomicAdd(&g_denom[t], sden[t]);
        atomicAdd(&g_cnt[t],   scnt[t]);
    }
}

// ---------------------------------------------------------------------------
// 2) tail rows of x_out:  U/denom if cam present, else running_mean
// ---------------------------------------------------------------------------
__global__ void tail_kernel(const float* __restrict__ rmean,
                            float* __restrict__ out)
{
    int idx = blockIdx.x * blockDim.x + threadIdx.x;
    if (idx < LN * CN) {
        int l = idx >> 11;
        float v = (g_cnt[l] > 0.0f) ? (g_U[idx] / g_denom[l]) : __ldg(&rmean[idx]);
        out[(size_t)BN * CN + idx] = v;
    }
}

// ---------------------------------------------------------------------------
// 3) adj fill (FROZEN R15/R16 pair version — 41.4us, at the ~5.1TB/s write
//    ceiling): alignment-perfect constant segmented fill.
// ---------------------------------------------------------------------------
__global__ void __launch_bounds__(256) adj_kernel(float* __restrict__ out)
{
    const int p = blockIdx.x;                     // pair index: rows 2p, 2p+1
    const int t = threadIdx.x;

    const float DA = rsqrtf(4098.0f);   // rgb sample
    const float DB = rsqrtf(4100.0f);   // ir sample
    const float DC = rsqrtf(4097.0f);   // cam node

    float4* pr = (float4*)(out + ADJ_OFF + (size_t)p * 2 * MN);

    if (p < 4096) {
        float lo, hi, ta, tb;
        if (p < 2048) { lo = DA * DA; hi = 0.0f;    ta = 0.0f;    tb = DA * DC; }
        else          { lo = 0.0f;    hi = DB * DB; ta = DB * DC; tb = 0.0f;    }

        const float4 LO4   = make_float4(lo, lo, lo, lo);
        const float4 HI4   = make_float4(hi, hi, hi, hi);
        const float4 TA4   = make_float4(ta, ta, ta, ta);
        const float4 Q2049 = make_float4(tb, tb, lo, lo);
        const float4 Q3073 = make_float4(lo, lo, hi, hi);
        const float4 Q4097 = make_float4(hi, hi, ta, ta);
        const float4 Q4098 = make_float4(ta, ta, tb, tb);

#pragma unroll
        for (int k = 0; k < 17; ++k) {
            const int q = t + 256 * k;
            if (q >= 4099) break;
            float4 v;
            if      (q < 1024)  v = LO4;
            else if (q < 2048)  v = HI4;
            else if (q == 2048) v = TA4;
            else if (q == 2049) v = Q2049;
            else if (q < 3073)  v = LO4;
            else if (q == 3073) v = Q3073;
            else if (q < 4097)  v = HI4;
            else if (q == 4097) v = Q4097;
            else                v = Q4098;
            __stcs(&pr[q], v);
        }
    } else {
        const int rE = 2 * p;                     // 8192 / 8194 / 8196
        const float DCA = DC * DA, DCB = DC * DB, DC2 = DC * DC;
        for (int k = 0; k < 17; ++k) {
            const int q = t + 256 * k;
            if (q >= 4099) break;
            float vv[4];
#pragma unroll
            for (int j = 0; j < 4; ++j) {
                const int e = 4 * q + j;
                const int r = rE + (e >= MN ? 1 : 0);
                const int c = e - (e >= MN ? MN : 0);
                const bool rgbCam = (r < BN + 4);
                float v;
                if (c < HALF)      v = rgbCam ? 0.0f : DCA;
                else if (c < BN)   v = rgbCam ? DCB : 0.0f;
                else               v = (c == r) ? DC2 : 0.0f;
                vv[j] = v;
            }
            __stcs(&pr[q], make_float4(vv[0], vv[1], vv[2], vv[3]));
        }
    }
}

// ---------------------------------------------------------------------------
// Launch: THREE-way fork. Copy engine moves x -> x_out (no SM resources);
// adj on least-priority stream; pass chain (score-only) on main. Join all.
// ---------------------------------------------------------------------------
extern "C" void kernel_launch(void* const* d_in, const int* in_sizes, int n_in,
                              void* d_out, int out_size)
{
    const float* x = nullptr; const int* cams = nullptr;
    const float* att_w = nullptr; const float* att_b = nullptr;
    const float* rmean = nullptr;

    for (int i = 0; i < n_in; ++i) {
        const int sz = in_sizes[i];
        if      (sz == BN * CN)           x = (const float*)d_in[i];
        else if (sz == BN)                cams = (const int*)d_in[i];
        else if (sz == LN * CN) { if (!att_w) att_w = (const float*)d_in[i];
                                  else        rmean = (const float*)d_in[i]; }
        else if (sz == LN)                att_b = (const float*)d_in[i];
    }

    float* out = (float*)d_out;

    static cudaStream_t s2 = nullptr, s3 = nullptr;
    static cudaEvent_t evFork = nullptr, evJoin2 = nullptr, evJoin3 = nullptr;
    if (s2 == nullptr) {
        int loPri = 0, hiPri = 0;
        cudaDeviceGetStreamPriorityRange(&loPri, &hiPri);
        cudaStreamCreateWithPriority(&s2, cudaStreamNonBlocking, loPri);
        cudaStreamCreateWithFlags(&s3, cudaStreamNonBlocking);
        cudaEventCreateWithFlags(&evFork,  cudaEventDisableTiming);
        cudaEventCreateWithFlags(&evJoin2, cudaEventDisableTiming);
        cudaEventCreateWithFlags(&evJoin3, cudaEventDisableTiming);
    }

    cudaEventRecord(evFork, 0);

    // main chain: score-only pass + tail
    zero_kernel<<<48, 256>>>();
    pass_kernel<<<128, 256>>>(x, cams, att_w, att_b);
    tail_kernel<<<48, 256>>>(rmean, out);

    // copy engine: x -> x_out rows [0, BN)
    cudaStreamWaitEvent(s3, evFork, 0);
    cudaMemcpyAsync(out, x, (size_t)BN * CN * sizeof(float),
                    cudaMemcpyDeviceToDevice, s3);
    cudaEventRecord(evJoin3, s3);

    // adj fill on low-priority stream
    cudaStreamWaitEvent(s2, evFork, 0);
    adj_kernel<<<4099, 256, 0, s2>>>(out);
    cudaEventRecord(evJoin2, s2);

    // join everything
    cudaStreamWaitEvent(0, evJoin2, 0);
    cudaStreamWaitEvent(0, evJoin3, 0);
}